// round 13
// baseline (speedup 1.0000x reference)
#include <cuda_runtime.h>

#define NN   100000
#define NE   3200000
#define INC  512
#define HIDC 256
#define OUTC 16
#define KITER 10

// ---------------- static scratch ----------------
__device__ float g_hid[(size_t)NN * HIDC];   // MLP hidden, 102.4 MB
__device__ float g_h0[NN * OUTC];            // x0
__device__ float g_hA[NN * OUTC];
__device__ float g_hB[NN * OUTC];
__device__ float g_dis[NN];                  // deg^{-1/2}
__device__ int   g_degc[NN];
__device__ int   g_rowptr[NN + 1];
__device__ int   g_cursor[NN];
__device__ int2  g_csr[NE];                  // (src, bits(0.9*dis_s*dis_d))
__device__ int   g_partials[128];
__device__ int   g_is64;

// ---------------- init: zero degc + dtype probe ----------------
__global__ void k_init(const unsigned* __restrict__ w) {
    int i = blockIdx.x * 256 + threadIdx.x;
    if (i < NN) g_degc[i] = 0;
    if (blockIdx.x == 0 && threadIdx.x == 0) {
        unsigned h = 0u;
#pragma unroll
        for (int j = 0; j < 16; j++) h |= w[2 * j + 1];
        g_is64 = (h == 0u) ? 1 : 0;
    }
}

__global__ void k_count(const void* __restrict__ eiv) {
    int e = blockIdx.x * 256 + threadIdx.x;
    if (e >= NE) return;
    int d;
    if (g_is64) {
        const long long* ei = (const long long*)eiv;
        long long s = ei[e];
        d = (int)ei[NE + e];
        if ((unsigned long long)s >= NN || (unsigned)d >= NN) return;
    } else {
        const int* ei = (const int*)eiv;
        int s = ei[e];
        d = ei[NE + e];
        if ((unsigned)s >= NN || (unsigned)d >= NN) return;
    }
    atomicAdd(&g_degc[d], 1);
}

// scan chunk 1024: block sums + dis
__global__ void k_scan1() {
    __shared__ int sh[1024];
    int i = blockIdx.x * 1024 + threadIdx.x;
    int v = (i < NN) ? g_degc[i] : 0;
    if (i < NN) g_dis[i] = rsqrtf((float)(v + 1));   // +1 self-loop
    sh[threadIdx.x] = v;
    __syncthreads();
    for (int off = 512; off > 0; off >>= 1) {
        if (threadIdx.x < off) sh[threadIdx.x] += sh[threadIdx.x + off];
        __syncthreads();
    }
    if (threadIdx.x == 0) g_partials[blockIdx.x] = sh[0];
}

__global__ void k_scan2(int nblocks) {
    if (threadIdx.x == 0) {
        int off = 0;
        for (int b = 0; b < nblocks; b++) { int t = g_partials[b]; g_partials[b] = off; off += t; }
        g_rowptr[NN] = off;
    }
}

__global__ void k_scan3() {
    __shared__ int sh[1024];
    int i = blockIdx.x * 1024 + threadIdx.x;
    int v = (i < NN) ? g_degc[i] : 0;
    sh[threadIdx.x] = v;
    __syncthreads();
    for (int off = 1; off < 1024; off <<= 1) {
        int t = (threadIdx.x >= off) ? sh[threadIdx.x - off] : 0;
        __syncthreads();
        sh[threadIdx.x] += t;
        __syncthreads();
    }
    if (i < NN) {
        int excl = sh[threadIdx.x] - v + g_partials[blockIdx.x];
        g_rowptr[i] = excl;
        g_cursor[i] = excl;
    }
}

__global__ void k_scatter(const void* __restrict__ eiv) {
    int e = blockIdx.x * 256 + threadIdx.x;
    if (e >= NE) return;
    int s, d;
    if (g_is64) {
        const long long* ei = (const long long*)eiv;
        s = (int)ei[e];
        d = (int)ei[NE + e];
        if ((unsigned long long)ei[e] >= NN || (unsigned)d >= NN) return;
    } else {
        const int* ei = (const int*)eiv;
        s = ei[e];
        d = ei[NE + e];
        if ((unsigned)s >= NN || (unsigned)d >= NN) return;
    }
    int pos = atomicAdd(&g_cursor[d], 1);
    float w = 0.9f * g_dis[s] * g_dis[d];
    g_csr[pos] = make_int2(s, __float_as_int(w));
}

// ---------------- GEMM1: tf32 mma.sync, 128x128x32 block tile ----------------
// grid = (HIDC/128, NN/128): x-fastest enumeration puts the two bn-twins of each
// bm adjacent in schedule order -> co-resident -> X tile hits L2 on second use.
#define ASTR 36
#define BSTR 136

__device__ __forceinline__ void mma_tf32(float* c,
        unsigned a0, unsigned a1, unsigned a2, unsigned a3,
        unsigned b0, unsigned b1) {
    asm volatile(
        "mma.sync.aligned.m16n8k8.row.col.f32.tf32.tf32.f32 "
        "{%0,%1,%2,%3}, {%4,%5,%6,%7}, {%8,%9}, {%0,%1,%2,%3};\n"
        : "+f"(c[0]), "+f"(c[1]), "+f"(c[2]), "+f"(c[3])
        : "r"(a0), "r"(a1), "r"(a2), "r"(a3), "r"(b0), "r"(b1));
}

__device__ __forceinline__ unsigned f2tf32(float f) {
    unsigned u;
    asm("cvt.rna.tf32.f32 %0, %1;" : "=r"(u) : "f"(f));
    return u;
}

__global__ __launch_bounds__(256) void k_gemm1(const float* __restrict__ X,
                                               const float* __restrict__ W1,
                                               const float* __restrict__ B1) {
    __shared__ unsigned As[128 * ASTR];   // 18432 B
    __shared__ unsigned Bs[32 * BSTR];    // 17408 B
    int tid = threadIdx.x;
    int bm = blockIdx.y * 128;
    int bn = blockIdx.x * 128;
    int warp = tid >> 5, lane = tid & 31;
    int wm = warp >> 2, wn = warp & 3;          // warp tile 64x32
    int gid = lane >> 2, tid4 = lane & 3;

    float acc[4][4][4];
#pragma unroll
    for (int i = 0; i < 4; i++)
#pragma unroll
        for (int j = 0; j < 4; j++)
#pragma unroll
            for (int k = 0; k < 4; k++) acc[i][j][k] = 0.f;

    int arow = tid >> 1;             // 0..127
    int akv  = (tid & 1) * 16;       // 0 / 16
    int grow = bm + arow;
    bool aok = grow < NN;
    const float* aptr = X + (size_t)grow * INC + akv;

    int brow = tid >> 3;             // 0..31
    int bcv  = (tid & 7) * 16;       // 0..112
    const float* bptr = W1 + (size_t)brow * HIDC + bn + bcv;

    for (int k0 = 0; k0 < INC; k0 += 32) {
#pragma unroll
        for (int j = 0; j < 4; j++) {
            float4 v = aok ? *(const float4*)(aptr + k0 + j * 4)
                           : make_float4(0.f, 0.f, 0.f, 0.f);
            uint4 u;
            u.x = f2tf32(v.x); u.y = f2tf32(v.y);
            u.z = f2tf32(v.z); u.w = f2tf32(v.w);
            *(uint4*)&As[arow * ASTR + akv + j * 4] = u;
        }
#pragma unroll
        for (int j = 0; j < 4; j++) {
            float4 v = *(const float4*)(bptr + (size_t)k0 * HIDC + j * 4);
            uint4 u;
            u.x = f2tf32(v.x); u.y = f2tf32(v.y);
            u.z = f2tf32(v.z); u.w = f2tf32(v.w);
            *(uint4*)&Bs[brow * BSTR + bcv + j * 4] = u;
        }
        __syncthreads();
#pragma unroll
        for (int s = 0; s < 4; s++) {
            unsigned b[4][2];
#pragma unroll
            for (int nf = 0; nf < 4; nf++) {
                int col = wn * 32 + nf * 8 + gid;
                b[nf][0] = Bs[(s * 8 + tid4) * BSTR + col];
                b[nf][1] = Bs[(s * 8 + tid4 + 4) * BSTR + col];
            }
#pragma unroll
            for (int mf = 0; mf < 4; mf++) {
                int r = wm * 64 + mf * 16 + gid;
                unsigned a0 = As[r * ASTR + s * 8 + tid4];
                unsigned a1 = As[(r + 8) * ASTR + s * 8 + tid4];
                unsigned a2 = As[r * ASTR + s * 8 + tid4 + 4];
                unsigned a3 = As[(r + 8) * ASTR + s * 8 + tid4 + 4];
#pragma unroll
                for (int nf = 0; nf < 4; nf++)
                    mma_tf32(acc[mf][nf], a0, a1, a2, a3, b[nf][0], b[nf][1]);
            }
        }
        __syncthreads();
    }
    // epilogue: bias + relu -> g_hid
#pragma unroll
    for (int mf = 0; mf < 4; mf++) {
#pragma unroll
        for (int nf = 0; nf < 4; nf++) {
            int col = bn + wn * 32 + nf * 8 + tid4 * 2;
            float bb0 = B1[col], bb1 = B1[col + 1];
            int r0 = bm + wm * 64 + mf * 16 + gid;
            if (r0 < NN) {
                float2 v;
                v.x = fmaxf(acc[mf][nf][0] + bb0, 0.f);
                v.y = fmaxf(acc[mf][nf][1] + bb1, 0.f);
                *(float2*)&g_hid[(size_t)r0 * HIDC + col] = v;
            }
            int r1 = r0 + 8;
            if (r1 < NN) {
                float2 v;
                v.x = fmaxf(acc[mf][nf][2] + bb0, 0.f);
                v.y = fmaxf(acc[mf][nf][3] + bb1, 0.f);
                *(float2*)&g_hid[(size_t)r1 * HIDC + col] = v;
            }
        }
    }
}

// ---------------- GEMM2: warp-per-node, memory bound ----------------
__global__ __launch_bounds__(256) void k_gemm2(const float* __restrict__ W2,
                                               const float* __restrict__ B2) {
    __shared__ float w2s[HIDC * OUTC];  // transposed [c][k], 16 KB
    int tid = threadIdx.x;
    for (int i = tid; i < HIDC * OUTC; i += 256)
        w2s[i] = W2[(i & (HIDC - 1)) * OUTC + (i >> 8)];
    __syncthreads();

    int warp = tid >> 5, lane = tid & 31;
    int n = blockIdx.x * 8 + warp;
    if (n >= NN) return;

    float acc[OUTC];
#pragma unroll
    for (int c = 0; c < OUTC; c++) acc[c] = 0.f;

    const float* hrow = &g_hid[(size_t)n * HIDC];
#pragma unroll
    for (int j = 0; j < HIDC / 32; j++) {
        int k = lane + 32 * j;
        float v = hrow[k];
#pragma unroll
        for (int c = 0; c < OUTC; c++) acc[c] += v * w2s[c * HIDC + k];
    }
#pragma unroll
    for (int c = 0; c < OUTC; c++) {
#pragma unroll
        for (int off = 16; off > 0; off >>= 1)
            acc[c] += __shfl_down_sync(0xffffffffu, acc[c], off);
    }
    if (lane == 0) {
#pragma unroll
        for (int c = 0; c < OUTC; c++)
            g_h0[n * OUTC + c] = acc[c] + B2[c];
    }
}

// ---------------- APPNP propagation: warp-per-node, 2-deep pipelined gather ----
__device__ __forceinline__ const float* buf_sel(int s) {
    return (s == 0) ? g_h0 : ((s == 1) ? g_hA : g_hB);
}
__device__ __forceinline__ float* buf_sel_w(int s) {
    return (s == 1) ? g_hA : g_hB;
}

template <bool LAST>
__global__ __launch_bounds__(256) void k_prop(int si, int so, float* __restrict__ out) {
    const float4* __restrict__ hin4 = (const float4*)buf_sel(si);
    int tid = threadIdx.x;
    int warp = tid >> 5, lane = tid & 31;
    int n = blockIdx.x * 8 + warp;
    if (n >= NN) return;
    int quad = lane >> 2, ql = lane & 3;

    int start = g_rowptr[n];
    int end = g_rowptr[n + 1];
    float4 acc = make_float4(0.f, 0.f, 0.f, 0.f);
    int e = start + quad;
    // 2 edges in flight per quad (deeper MLP against L2 latency)
    for (; e + 8 < end; e += 16) {
        int2 p0 = g_csr[e];
        int2 p1 = g_csr[e + 8];
        float w0 = __int_as_float(p0.y);
        float w1 = __int_as_float(p1.y);
        float4 v0 = hin4[p0.x * 4 + ql];
        float4 v1 = hin4[p1.x * 4 + ql];
        acc.x += w0 * v0.x; acc.y += w0 * v0.y; acc.z += w0 * v0.z; acc.w += w0 * v0.w;
        acc.x += w1 * v1.x; acc.y += w1 * v1.y; acc.z += w1 * v1.z; acc.w += w1 * v1.w;
    }
    if (e < end) {
        int2 p = g_csr[e];
        float w = __int_as_float(p.y);
        float4 v = hin4[p.x * 4 + ql];
        acc.x += w * v.x; acc.y += w * v.y; acc.z += w * v.z; acc.w += w * v.w;
    }
#pragma unroll
    for (int off = 4; off <= 16; off <<= 1) {
        acc.x += __shfl_xor_sync(0xffffffffu, acc.x, off);
        acc.y += __shfl_xor_sync(0xffffffffu, acc.y, off);
        acc.z += __shfl_xor_sync(0xffffffffu, acc.z, off);
        acc.w += __shfl_xor_sync(0xffffffffu, acc.w, off);
    }
    if (lane < 4) {
        float dv = g_dis[n];
        float ws = 0.9f * dv * dv;
        float4 hs = hin4[n * 4 + ql];
        float4 h0v = ((const float4*)g_h0)[n * 4 + ql];
        float4 val;
        val.x = acc.x + ws * hs.x + 0.1f * h0v.x;
        val.y = acc.y + ws * hs.y + 0.1f * h0v.y;
        val.z = acc.z + ws * hs.z + 0.1f * h0v.z;
        val.w = acc.w + ws * hs.w + 0.1f * h0v.w;
        if (!LAST) {
            ((float4*)buf_sel_w(so))[n * 4 + ql] = val;
        } else {
            float m = fmaxf(fmaxf(val.x, val.y), fmaxf(val.z, val.w));
            m = fmaxf(m, __shfl_xor_sync(0x0000000Fu, m, 1));
            m = fmaxf(m, __shfl_xor_sync(0x0000000Fu, m, 2));
            float s = expf(val.x - m) + expf(val.y - m)
                    + expf(val.z - m) + expf(val.w - m);
            s += __shfl_xor_sync(0x0000000Fu, s, 1);
            s += __shfl_xor_sync(0x0000000Fu, s, 2);
            float ls = logf(s) + m;
            float4 o;
            o.x = val.x - ls; o.y = val.y - ls; o.z = val.z - ls; o.w = val.w - ls;
            ((float4*)out)[n * 4 + ql] = o;
        }
    }
}

// ---------------- launch ----------------
extern "C" void kernel_launch(void* const* d_in, const int* in_sizes, int n_in,
                              void* d_out, int out_size) {
    const float* x  = (const float*)d_in[0];
    const void*  ei = (const void*)d_in[1];
    const float* W1 = (const float*)d_in[2];
    const float* b1 = (const float*)d_in[3];
    const float* W2 = (const float*)d_in[4];
    const float* b2 = (const float*)d_in[5];
    float* out = (float*)d_out;

    const int scan_blocks = (NN + 1023) / 1024;  // 98

    k_init<<<(NN + 255) / 256, 256>>>((const unsigned*)ei);            // 1
    k_count<<<(NE + 255) / 256, 256>>>(ei);                            // 2
    k_scan1<<<scan_blocks, 1024>>>();                                  // 3
    // gemm1 has no preproc dependency; slot 4 = ncu capture slot
    dim3 g1(HIDC / 128, (NN + 127) / 128);                             // (2, 782)
    k_gemm1<<<g1, 256>>>(x, W1, b1);                                   // 4
    k_scan2<<<1, 32>>>(scan_blocks);                                   // 5
    k_scan3<<<scan_blocks, 1024>>>();                                  // 6
    k_scatter<<<(NE + 255) / 256, 256>>>(ei);                          // 7
    k_gemm2<<<(NN + 7) / 8, 256>>>(W2, b2);                            // 8

    // APPNP: h0 -> A -> B -> ... (10 iters total, last fused with log_softmax)
    int pb = (NN + 7) / 8;
    k_prop<false><<<pb, 256>>>(0, 1, nullptr);
    int cur = 1;
    for (int i = 1; i < KITER - 1; i++) {
        int nxt = (cur == 1) ? 2 : 1;
        k_prop<false><<<pb, 256>>>(cur, nxt, nullptr);
        cur = nxt;
    }
    k_prop<true><<<pb, 256>>>(cur, 0, out);
}

// round 15
// speedup vs baseline: 1.0344x; 1.0344x over previous
#include <cuda_runtime.h>
#include <cuda_fp16.h>

#define NN   100000
#define NE   3200000
#define INC  512
#define HIDC 256
#define OUTC 16
#define KITER 10

// ---------------- static scratch ----------------
__device__ float g_hid[(size_t)NN * HIDC];   // MLP hidden, 102.4 MB
__device__ float g_h0[NN * OUTC];            // x0
__device__ float g_hA[NN * OUTC];
__device__ float g_hB[NN * OUTC];
__device__ float g_dis[NN];                  // deg^{-1/2}
__device__ int   g_degc[NN];
__device__ int   g_rowptr[NN + 1];
__device__ int   g_cursor[NN];
__device__ int2  g_csr[NE];                  // (src, bits(0.9*dis_s*dis_d))
__device__ int   g_partials[128];
__device__ int   g_is64;

// ---------------- init: zero degc + dtype probe ----------------
__global__ void k_init(const unsigned* __restrict__ w) {
    int i = blockIdx.x * 256 + threadIdx.x;
    if (i < NN) g_degc[i] = 0;
    if (blockIdx.x == 0 && threadIdx.x == 0) {
        unsigned h = 0u;
#pragma unroll
        for (int j = 0; j < 16; j++) h |= w[2 * j + 1];
        g_is64 = (h == 0u) ? 1 : 0;
    }
}

__global__ void k_count(const void* __restrict__ eiv) {
    int e = blockIdx.x * 256 + threadIdx.x;
    if (e >= NE) return;
    int d;
    if (g_is64) {
        const long long* ei = (const long long*)eiv;
        long long s = ei[e];
        d = (int)ei[NE + e];
        if ((unsigned long long)s >= NN || (unsigned)d >= NN) return;
    } else {
        const int* ei = (const int*)eiv;
        int s = ei[e];
        d = ei[NE + e];
        if ((unsigned)s >= NN || (unsigned)d >= NN) return;
    }
    atomicAdd(&g_degc[d], 1);
}

// scan chunk 1024: block sums + dis
__global__ void k_scan1() {
    __shared__ int sh[1024];
    int i = blockIdx.x * 1024 + threadIdx.x;
    int v = (i < NN) ? g_degc[i] : 0;
    if (i < NN) g_dis[i] = rsqrtf((float)(v + 1));   // +1 self-loop
    sh[threadIdx.x] = v;
    __syncthreads();
    for (int off = 512; off > 0; off >>= 1) {
        if (threadIdx.x < off) sh[threadIdx.x] += sh[threadIdx.x + off];
        __syncthreads();
    }
    if (threadIdx.x == 0) g_partials[blockIdx.x] = sh[0];
}

__global__ void k_scan2(int nblocks) {
    if (threadIdx.x == 0) {
        int off = 0;
        for (int b = 0; b < nblocks; b++) { int t = g_partials[b]; g_partials[b] = off; off += t; }
        g_rowptr[NN] = off;
    }
}

__global__ void k_scan3() {
    __shared__ int sh[1024];
    int i = blockIdx.x * 1024 + threadIdx.x;
    int v = (i < NN) ? g_degc[i] : 0;
    sh[threadIdx.x] = v;
    __syncthreads();
    for (int off = 1; off < 1024; off <<= 1) {
        int t = (threadIdx.x >= off) ? sh[threadIdx.x - off] : 0;
        __syncthreads();
        sh[threadIdx.x] += t;
        __syncthreads();
    }
    if (i < NN) {
        int excl = sh[threadIdx.x] - v + g_partials[blockIdx.x];
        g_rowptr[i] = excl;
        g_cursor[i] = excl;
    }
}

__global__ void k_scatter(const void* __restrict__ eiv) {
    int e = blockIdx.x * 256 + threadIdx.x;
    if (e >= NE) return;
    int s, d;
    if (g_is64) {
        const long long* ei = (const long long*)eiv;
        s = (int)ei[e];
        d = (int)ei[NE + e];
        if ((unsigned long long)ei[e] >= NN || (unsigned)d >= NN) return;
    } else {
        const int* ei = (const int*)eiv;
        s = ei[e];
        d = ei[NE + e];
        if ((unsigned)s >= NN || (unsigned)d >= NN) return;
    }
    int pos = atomicAdd(&g_cursor[d], 1);
    float w = 0.9f * g_dis[s] * g_dis[d];
    g_csr[pos] = make_int2(s, __float_as_int(w));
}

// ---------------- GEMM1: fp16 mma.sync m16n8k16, 128x128x64 block tile -------
// fp16 mantissa == tf32 mantissa (11 bits) -> same rounding error, 2x FLOP/instr,
// each u32 carries 2 elements -> LDS/STS/smem traffic halved vs tf32 k8.
#define ASTR 36    // u32 stride: 32 used (64 fp16) + 4 pad
#define BSTR 136   // u32 stride: 128 used + 8 pad

__device__ __forceinline__ void mma_fp16(float* c,
        unsigned a0, unsigned a1, unsigned a2, unsigned a3,
        unsigned b0, unsigned b1) {
    asm volatile(
        "mma.sync.aligned.m16n8k16.row.col.f32.f16.f16.f32 "
        "{%0,%1,%2,%3}, {%4,%5,%6,%7}, {%8,%9}, {%0,%1,%2,%3};\n"
        : "+f"(c[0]), "+f"(c[1]), "+f"(c[2]), "+f"(c[3])
        : "r"(a0), "r"(a1), "r"(a2), "r"(a3), "r"(b0), "r"(b1));
}

__device__ __forceinline__ unsigned pack_h2(float lo, float hi) {
    __half2 h = __floats2half2_rn(lo, hi);   // low half = lo (lower k index)
    return *(unsigned*)&h;
}

__global__ __launch_bounds__(256) void k_gemm1(const float* __restrict__ X,
                                               const float* __restrict__ W1,
                                               const float* __restrict__ B1) {
    __shared__ unsigned As[128 * ASTR];   // 18432 B (128 rows x 64 fp16)
    __shared__ unsigned Bs[32 * BSTR];    // 17408 B (32 k-pairs x 128 n)
    int tid = threadIdx.x;
    int bm = blockIdx.y * 128;
    int bn = blockIdx.x * 128;
    int warp = tid >> 5, lane = tid & 31;
    int wm = warp >> 2, wn = warp & 3;          // warp tile 64x32
    int gid = lane >> 2, tid4 = lane & 3;

    float acc[4][4][4];
#pragma unroll
    for (int i = 0; i < 4; i++)
#pragma unroll
        for (int j = 0; j < 4; j++)
#pragma unroll
            for (int k = 0; k < 4; k++) acc[i][j][k] = 0.f;

    int arow = tid >> 1;             // 0..127
    int ahalf = tid & 1;             // covers u32 cols [0,16) or [16,32)
    int grow = bm + arow;
    bool aok = grow < NN;
    const float* aptr = X + (size_t)grow * INC;

    int bkp = tid >> 3;              // k-pair row 0..31
    int bcv = (tid & 7) * 16;        // n columns [bcv, bcv+16)
    const float* bptr0 = W1 + (size_t)(2 * bkp) * HIDC + bn + bcv;       // even k row
    const float* bptr1 = W1 + (size_t)(2 * bkp + 1) * HIDC + bn + bcv;   // odd k row

    for (int k0 = 0; k0 < INC; k0 += 64) {     // 64 fp16 k-elements per stage
        // A: pack adjacent k into half2. Each thread: 32 fp32 -> 16 u32.
#pragma unroll
        for (int j = 0; j < 4; j++) {
            int kf = k0 + ahalf * 32 + j * 8;
            float4 va = aok ? *(const float4*)(aptr + kf)
                            : make_float4(0.f, 0.f, 0.f, 0.f);
            float4 vb = aok ? *(const float4*)(aptr + kf + 4)
                            : make_float4(0.f, 0.f, 0.f, 0.f);
            uint4 u;
            u.x = pack_h2(va.x, va.y); u.y = pack_h2(va.z, va.w);
            u.z = pack_h2(vb.x, vb.y); u.w = pack_h2(vb.z, vb.w);
            *(uint4*)&As[arow * ASTR + ahalf * 16 + j * 4] = u;
        }
        // B: pack (even k row, odd k row) per n into half2. 16 u32 per thread.
#pragma unroll
        for (int j = 0; j < 4; j++) {
            float4 r0 = *(const float4*)(bptr0 + (size_t)k0 * HIDC + j * 4);
            float4 r1 = *(const float4*)(bptr1 + (size_t)k0 * HIDC + j * 4);
            uint4 u;
            u.x = pack_h2(r0.x, r1.x); u.y = pack_h2(r0.y, r1.y);
            u.z = pack_h2(r0.z, r1.z); u.w = pack_h2(r0.w, r1.w);
            *(uint4*)&Bs[bkp * BSTR + bcv + j * 4] = u;
        }
        __syncthreads();
#pragma unroll
        for (int s = 0; s < 4; s++) {          // 4 x k16 sub-steps
            unsigned b[4][2];
#pragma unroll
            for (int nf = 0; nf < 4; nf++) {
                int col = wn * 32 + nf * 8 + gid;
                b[nf][0] = Bs[(s * 8 + tid4) * BSTR + col];
                b[nf][1] = Bs[(s * 8 + tid4 + 4) * BSTR + col];
            }
#pragma unroll
            for (int mf = 0; mf < 4; mf++) {
                int r = wm * 64 + mf * 16 + gid;
                unsigned a0 = As[r * ASTR + s * 8 + tid4];
                unsigned a1 = As[(r + 8) * ASTR + s * 8 + tid4];
                unsigned a2 = As[r * ASTR + s * 8 + tid4 + 4];
                unsigned a3 = As[(r + 8) * ASTR + s * 8 + tid4 + 4];
#pragma unroll
                for (int nf = 0; nf < 4; nf++)
                    mma_fp16(acc[mf][nf], a0, a1, a2, a3, b[nf][0], b[nf][1]);
            }
        }
        __syncthreads();
    }
    // epilogue: bias + relu -> g_hid (C layout identical to tf32 k8)
#pragma unroll
    for (int mf = 0; mf < 4; mf++) {
#pragma unroll
        for (int nf = 0; nf < 4; nf++) {
            int col = bn + wn * 32 + nf * 8 + tid4 * 2;
            float bb0 = B1[col], bb1 = B1[col + 1];
            int r0 = bm + wm * 64 + mf * 16 + gid;
            if (r0 < NN) {
                float2 v;
                v.x = fmaxf(acc[mf][nf][0] + bb0, 0.f);
                v.y = fmaxf(acc[mf][nf][1] + bb1, 0.f);
                *(float2*)&g_hid[(size_t)r0 * HIDC + col] = v;
            }
            int r1 = r0 + 8;
            if (r1 < NN) {
                float2 v;
                v.x = fmaxf(acc[mf][nf][2] + bb0, 0.f);
                v.y = fmaxf(acc[mf][nf][3] + bb1, 0.f);
                *(float2*)&g_hid[(size_t)r1 * HIDC + col] = v;
            }
        }
    }
}

// ---------------- GEMM2: warp-per-node, memory bound ----------------
__global__ __launch_bounds__(256) void k_gemm2(const float* __restrict__ W2,
                                               const float* __restrict__ B2) {
    __shared__ float w2s[HIDC * OUTC];  // transposed [c][k], 16 KB
    int tid = threadIdx.x;
    for (int i = tid; i < HIDC * OUTC; i += 256)
        w2s[i] = W2[(i & (HIDC - 1)) * OUTC + (i >> 8)];
    __syncthreads();

    int warp = tid >> 5, lane = tid & 31;
    int n = blockIdx.x * 8 + warp;
    if (n >= NN) return;

    float acc[OUTC];
#pragma unroll
    for (int c = 0; c < OUTC; c++) acc[c] = 0.f;

    const float* hrow = &g_hid[(size_t)n * HIDC];
#pragma unroll
    for (int j = 0; j < HIDC / 32; j++) {
        int k = lane + 32 * j;
        float v = hrow[k];
#pragma unroll
        for (int c = 0; c < OUTC; c++) acc[c] += v * w2s[c * HIDC + k];
    }
#pragma unroll
    for (int c = 0; c < OUTC; c++) {
#pragma unroll
        for (int off = 16; off > 0; off >>= 1)
            acc[c] += __shfl_down_sync(0xffffffffu, acc[c], off);
    }
    if (lane == 0) {
#pragma unroll
        for (int c = 0; c < OUTC; c++)
            g_h0[n * OUTC + c] = acc[c] + B2[c];
    }
}

// ---------------- APPNP propagation: warp-per-node, 2-deep pipelined gather ----
__device__ __forceinline__ const float* buf_sel(int s) {
    return (s == 0) ? g_h0 : ((s == 1) ? g_hA : g_hB);
}
__device__ __forceinline__ float* buf_sel_w(int s) {
    return (s == 1) ? g_hA : g_hB;
}

template <bool LAST>
__global__ __launch_bounds__(256) void k_prop(int si, int so, float* __restrict__ out) {
    const float4* __restrict__ hin4 = (const float4*)buf_sel(si);
    int tid = threadIdx.x;
    int warp = tid >> 5, lane = tid & 31;
    int n = blockIdx.x * 8 + warp;
    if (n >= NN) return;
    int quad = lane >> 2, ql = lane & 3;

    int start = g_rowptr[n];
    int end = g_rowptr[n + 1];
    float4 acc = make_float4(0.f, 0.f, 0.f, 0.f);
    int e = start + quad;
    for (; e + 8 < end; e += 16) {
        int2 p0 = g_csr[e];
        int2 p1 = g_csr[e + 8];
        float w0 = __int_as_float(p0.y);
        float w1 = __int_as_float(p1.y);
        float4 v0 = hin4[p0.x * 4 + ql];
        float4 v1 = hin4[p1.x * 4 + ql];
        acc.x += w0 * v0.x; acc.y += w0 * v0.y; acc.z += w0 * v0.z; acc.w += w0 * v0.w;
        acc.x += w1 * v1.x; acc.y += w1 * v1.y; acc.z += w1 * v1.z; acc.w += w1 * v1.w;
    }
    if (e < end) {
        int2 p = g_csr[e];
        float w = __int_as_float(p.y);
        float4 v = hin4[p.x * 4 + ql];
        acc.x += w * v.x; acc.y += w * v.y; acc.z += w * v.z; acc.w += w * v.w;
    }
#pragma unroll
    for (int off = 4; off <= 16; off <<= 1) {
        acc.x += __shfl_xor_sync(0xffffffffu, acc.x, off);
        acc.y += __shfl_xor_sync(0xffffffffu, acc.y, off);
        acc.z += __shfl_xor_sync(0xffffffffu, acc.z, off);
        acc.w += __shfl_xor_sync(0xffffffffu, acc.w, off);
    }
    if (lane < 4) {
        float dv = g_dis[n];
        float ws = 0.9f * dv * dv;
        float4 hs = hin4[n * 4 + ql];
        float4 h0v = ((const float4*)g_h0)[n * 4 + ql];
        float4 val;
        val.x = acc.x + ws * hs.x + 0.1f * h0v.x;
        val.y = acc.y + ws * hs.y + 0.1f * h0v.y;
        val.z = acc.z + ws * hs.z + 0.1f * h0v.z;
        val.w = acc.w + ws * hs.w + 0.1f * h0v.w;
        if (!LAST) {
            ((float4*)buf_sel_w(so))[n * 4 + ql] = val;
        } else {
            float m = fmaxf(fmaxf(val.x, val.y), fmaxf(val.z, val.w));
            m = fmaxf(m, __shfl_xor_sync(0x0000000Fu, m, 1));
            m = fmaxf(m, __shfl_xor_sync(0x0000000Fu, m, 2));
            float s = expf(val.x - m) + expf(val.y - m)
                    + expf(val.z - m) + expf(val.w - m);
            s += __shfl_xor_sync(0x0000000Fu, s, 1);
            s += __shfl_xor_sync(0x0000000Fu, s, 2);
            float ls = logf(s) + m;
            float4 o;
            o.x = val.x - ls; o.y = val.y - ls; o.z = val.z - ls; o.w = val.w - ls;
            ((float4*)out)[n * 4 + ql] = o;
        }
    }
}

// ---------------- launch ----------------
extern "C" void kernel_launch(void* const* d_in, const int* in_sizes, int n_in,
                              void* d_out, int out_size) {
    const float* x  = (const float*)d_in[0];
    const void*  ei = (const void*)d_in[1];
    const float* W1 = (const float*)d_in[2];
    const float* b1 = (const float*)d_in[3];
    const float* W2 = (const float*)d_in[4];
    const float* b2 = (const float*)d_in[5];
    float* out = (float*)d_out;

    const int scan_blocks = (NN + 1023) / 1024;  // 98

    k_init<<<(NN + 255) / 256, 256>>>((const unsigned*)ei);            // 1
    k_count<<<(NE + 255) / 256, 256>>>(ei);                            // 2
    k_scan1<<<scan_blocks, 1024>>>();                                  // 3
    dim3 g1(HIDC / 128, (NN + 127) / 128);                             // (2, 782)
    k_gemm1<<<g1, 256>>>(x, W1, b1);                                   // 4 = ncu slot
    k_scan2<<<1, 32>>>(scan_blocks);                                   // 5
    k_scan3<<<scan_blocks, 1024>>>();                                  // 6
    k_scatter<<<(NE + 255) / 256, 256>>>(ei);                          // 7
    k_gemm2<<<(NN + 7) / 8, 256>>>(W2, b2);                            // 8

    // APPNP: h0 -> A -> B -> ... (10 iters total, last fused with log_softmax)
    int pb = (NN + 7) / 8;
    k_prop<false><<<pb, 256>>>(0, 1, nullptr);
    int cur = 1;
    for (int i = 1; i < KITER - 1; i++) {
        int nxt = (cur == 1) ? 2 : 1;
        k_prop<false><<<pb, 256>>>(cur, nxt, nullptr);
        cur = nxt;
    }
    k_prop<true><<<pb, 256>>>(cur, 0, out);
}